// round 16
// baseline (speedup 1.0000x reference)
#include <cuda_runtime.h>
#include <cuda_bf16.h>
#include <math.h>

#define BATCH 32
#define EPSV 1e-6f
#define SCALV 5.0f

typedef unsigned long long u64;

// ---------------- scratch (static device globals; alloc-free) ----------------
__device__ float g_h1[2*BATCH*64*64*64];
__device__ float g_h2[2*BATCH*64*64*64];
__device__ float g_t1[BATCH*64*64*64];
__device__ float g_parts[2*BATCH*16*64*64];
__device__ float g_norm[BATCH*16*64*64];
__device__ float g_fxs[BATCH*32*64*64];
__device__ float g_enc[BATCH*48*64*64];
__device__ float g_h128[BATCH*32*128*128];
__device__ float g_mu[BATCH*16*2];
__device__ float g_Linv[BATCH*16*4];
__device__ float g_mua[BATCH*16*2];
__device__ float g_Linva[BATCH*16*4];
__device__ float g_alpha[BATCH*16*32];
__device__ float g_partial[1536];
__device__ float2 g_wc2[2*64*16*8];          // parity weights [grp(2)][cin][i(16)][k(8)]

// dup-weight pool.
// 12-slot padded layout (dy4 kernels, ACC=8): [g][cin/2][(cc*8+i)*12 + ky*4 + kx]
// 10-slot layout (old kernel, final conv): unchanged
#define OFF_ESW2 0
#define OFF_ESWP (OFF_ESW2 + 64*64*12)
#define OFF_EAW1 (OFF_ESWP + 16*64*12)
#define OFF_EAW2 (OFF_EAW1 + 64*64*12)
#define OFF_DW1  (OFF_EAW2 + 32*64*12)
#define OFF_DW3  (OFF_DW1  + 64*48*12)
#define DUP_TOTAL (OFF_DW3 + 3*32*10)
__device__ float2 g_dupw[DUP_TOTAL];

// ---------------- f32x2 packed helpers ----------------
__device__ __forceinline__ u64 pk2(float lo, float hi) {
    u64 r; asm("mov.b64 %0, {%1, %2};" : "=l"(r) : "f"(lo), "f"(hi)); return r;
}
__device__ __forceinline__ void upk2(u64 v, float& lo, float& hi) {
    asm("mov.b64 {%0, %1}, %2;" : "=f"(lo), "=f"(hi) : "l"(v));
}
__device__ __forceinline__ void fma2(u64& d, u64 a, u64 b) {
    asm("fma.rn.f32x2 %0, %1, %2, %0;" : "+l"(d) : "l"(a), "l"(b));
}
__device__ __forceinline__ unsigned sptr(const void* p) {
    return (unsigned)__cvta_generic_to_shared(p);
}
__device__ __forceinline__ void lds_v2u64(u64& a, u64& b, unsigned addr) {
    asm volatile("ld.shared.v2.u64 {%0, %1}, [%2];" : "=l"(a), "=l"(b) : "r"(addr));
}
__device__ __forceinline__ u64 lds_u64(unsigned addr) {
    u64 r; asm volatile("ld.shared.b64 %0, [%1];" : "=l"(r) : "r"(addr)); return r;
}

// ---------------- cp.async helpers ----------------
__device__ __forceinline__ void cp_async4(unsigned saddr, const void* gaddr, bool ok) {
    asm volatile("cp.async.ca.shared.global [%0], [%1], 4, %2;"
                 :: "r"(saddr), "l"(gaddr), "r"(ok ? 4 : 0));
}
__device__ __forceinline__ void cp_async16(unsigned saddr, const void* gaddr) {
    asm volatile("cp.async.cg.shared.global [%0], [%1], 16;" :: "r"(saddr), "l"(gaddr));
}
__device__ __forceinline__ void cp_commit() {
    asm volatile("cp.async.commit_group;");
}
__device__ __forceinline__ void cp_wait1() {
    asm volatile("cp.async.wait_group 1;");
}
__device__ __forceinline__ void cp_wait0() {
    asm volatile("cp.async.wait_group 0;");
}

// ---------------- reductions ----------------
__device__ __forceinline__ float warp_sum(float v) {
    #pragma unroll
    for (int o = 16; o; o >>= 1) v += __shfl_xor_sync(0xffffffffu, v, o);
    return v;
}
__device__ __forceinline__ float block_sum256(float v, float* red) {
    int tid = threadIdx.x;
    v = warp_sum(v);
    if ((tid & 31) == 0) red[tid >> 5] = v;
    __syncthreads();
    float r = 0.f;
    if (tid < 8) r = red[tid];
    if (tid < 32) r = warp_sum(r);
    if (tid == 0) red[0] = r;
    __syncthreads();
    float out = red[0];
    __syncthreads();
    return out;
}

// ============ weight duplication: 12-slot padded layout (dy4, ACC=8) ============
__global__ void dup_weights12_kernel(const float* __restrict__ src, float2* __restrict__ dst,
                                     int COUT, int CIN)
{
    int total = COUT * CIN * 12;
    int idx = blockIdx.x * 256 + threadIdx.x;
    if (idx >= total) return;
    int k12 = idx % 12;
    int t = idx / 12;
    int cin = t % CIN;
    int oc  = t / CIN;
    int g = oc >> 3, i = oc & 7;
    int c0h = cin >> 1, cc = cin & 1;
    int ky = k12 >> 2, kx = k12 & 3;
    float w = (kx < 3) ? src[((size_t)oc * CIN + cin) * 9 + ky * 3 + kx] : 0.f;
    dst[((size_t)(g * (CIN >> 1) + c0h) * (2 * 8 * 12)) + (cc * 8 + i) * 12 + k12] = make_float2(w, w);
}

// ============ weight duplication: 10-slot layout (old kernel) ============
__global__ void dup_weights_kernel(const float* __restrict__ src, float2* __restrict__ dst,
                                   int COUT, int CIN, int ACCv)
{
    int total = COUT * CIN * 10;
    int idx = blockIdx.x * 256 + threadIdx.x;
    if (idx >= total) return;
    int k = idx % 10;
    int t = idx / 10;
    int cin = t % CIN;
    int oc  = t / CIN;
    int g = oc / ACCv, i = oc % ACCv;
    int c0h = cin >> 1, cc = cin & 1;
    float w = (k < 9) ? src[((size_t)oc * CIN + cin) * 9 + k] : 0.f;
    dst[((size_t)(g * (CIN >> 1) + c0h) * 2 * ACCv + cc * ACCv + i) * 10 + k] = make_float2(w, w);
}

// ============ dy4 packed conv3x3, stride 1, SAME: 64x32 tile ============
// 256 threads; each thread 4 rows x 1 packed pair x 8 channels.
// Triple-buffered cp.async 2-channel staging, one barrier/stage. Dynamic smem.
#define DY4_SIN   (3 * 2 * 66 * 36)                 // floats
#define DY4_SMEM  (DY4_SIN * 4 + 3 * 192 * 8)       // bytes
template<int CIN, int COUT, int ACT>
__global__ __launch_bounds__(256, 2)
void conv3x3_dy4(const float* __restrict__ in,
                 const float2* __restrict__ dupw,
                 const float* __restrict__ bias,
                 float* __restrict__ out, int OH, int OW)
{
    extern __shared__ char dsm[];
    float* s_in = (float*)dsm;                       // [3][2][66][36]
    float2* s_w = (float2*)(dsm + DY4_SIN * 4);      // [3][192]

    constexpr int GROUPS = COUT / 8;
    constexpr int NS = CIN / 2;
    const int b   = blockIdx.z / GROUPS;
    const int grp = blockIdx.z % GROUPS;
    const int oc0 = grp * 8;
    const int tid = threadIdx.x;
    const int tx = tid & 15, ty = tid >> 4;
    const int oy0 = blockIdx.y * 64, ox0 = blockIdx.x * 32;

    const int sr0 = tid >> 3;        // staging rows 0..31 (+32, +64)
    const int sc0 = tid & 7;

    u64 acc[8][4];
    #pragma unroll
    for (int i = 0; i < 8; i++) {
        float bv = bias[oc0 + i];
        acc[i][0] = pk2(bv, bv);
        acc[i][1] = acc[i][0]; acc[i][2] = acc[i][0]; acc[i][3] = acc[i][0];
    }

    const unsigned inbase = sptr(s_in);
    const unsigned wbase  = sptr(s_w);
    const float2* wchunk = dupw + (size_t)grp * (CIN >> 1) * 192;
    const float* ipbase = in + (size_t)b * CIN * OH * OW;

    auto issue_stage = [&](int s) {
        const int buf = s % 3;
        const int c0 = 2 * s;
        #pragma unroll
        for (int cc = 0; cc < 2; cc++) {
            const float* ip = ipbase + (size_t)(c0 + cc) * OH * OW;
            unsigned sb = inbase + (unsigned)((buf * 2 + cc) * 66 * 36) * 4u;
            #pragma unroll
            for (int rp = 0; rp < 3; rp++) {
                int r = sr0 + rp * 32;
                if (rp < 2 || sr0 < 2) {             // r < 66
                    int iy = oy0 - 1 + r;
                    bool rowok = (iy >= 0) && (iy < OH);
                    const float* iprow = ip + iy * OW;
                    unsigned srow = sb + (unsigned)(r * 36) * 4u;
                    #pragma unroll
                    for (int j = 0; j < 5; j++) {
                        int c = sc0 + 8 * j;
                        if (j < 4 || c < 34) {
                            int ix = ox0 - 1 + c;
                            bool ok = rowok && (ix >= 0) && (ix < OW);
                            const float* ga = ok ? (iprow + ix) : ip;
                            cp_async4(srow + (unsigned)c * 4u, ga, ok);
                        }
                    }
                }
            }
        }
        // weights: 192 float2 = 1536B = 96 x 16B
        if (tid < 96) {
            const float2* wsrc = wchunk + (size_t)(c0 >> 1) * 192;
            cp_async16(wbase + (unsigned)(buf * 192 + tid * 2) * 8u, wsrc + tid * 2);
        }
    };

    issue_stage(0); cp_commit();
    issue_stage(1); cp_commit();

    for (int s = 0; s < NS; s++) {
        const int buf = s % 3;
        cp_wait1();
        __syncthreads();

        #pragma unroll
        for (int cc = 0; cc < 2; cc++) {
            u64 pr[6][3];
            #pragma unroll
            for (int r = 0; r < 6; r++) {
                unsigned a = inbase + (unsigned)((buf * 2 + cc) * 66 * 36 + (4 * ty + r) * 36 + 2 * tx) * 4u;
                u64 A = lds_u64(a);
                u64 B = lds_u64(a + 8);
                float a0, a1, b0, b1;
                upk2(A, a0, a1); upk2(B, b0, b1);
                pr[r][0] = A; pr[r][1] = pk2(a1, b0); pr[r][2] = B;
            }
            #pragma unroll
            for (int i = 0; i < 8; i++) {
                unsigned wa = wbase + (unsigned)(buf * 192 + (cc * 8 + i) * 12) * 8u;
                #pragma unroll
                for (int ky = 0; ky < 3; ky++) {
                    u64 w0, w1, w2;
                    lds_v2u64(w0, w1, wa + ky * 32);
                    w2 = lds_u64(wa + ky * 32 + 16);
                    #pragma unroll
                    for (int dy = 0; dy < 4; dy++) {
                        fma2(acc[i][dy], pr[dy + ky][0], w0);
                        fma2(acc[i][dy], pr[dy + ky][1], w1);
                        fma2(acc[i][dy], pr[dy + ky][2], w2);
                    }
                }
            }
        }
        if (s + 2 < NS) issue_stage(s + 2);
        cp_commit();
    }

    const int oy = oy0 + 4 * ty, ox = ox0 + 2 * tx;
    #pragma unroll
    for (int i = 0; i < 8; i++)
        #pragma unroll
        for (int dy = 0; dy < 4; dy++) {
            float v0, v1;
            upk2(acc[i][dy], v0, v1);
            if (ACT == 1) { v0 = fmaxf(v0, 0.f); v1 = fmaxf(v1, 0.f); }
            else if (ACT == 2) { v0 = 1.f / (1.f + expf(-v0)); v1 = 1.f / (1.f + expf(-v1)); }
            *reinterpret_cast<float2*>(out + (((size_t)b * COUT + oc0 + i) * OH + oy + dy) * OW + ox)
                = make_float2(v0, v1);
        }
}

// ============ old packed conv3x3 (kept for the 32->3 final conv) ============
template<int CIN, int COUT, int ACC, int ACT>
__global__ __launch_bounds__(256, 2)
void conv3x3_f2(const float* __restrict__ in,
                const float2* __restrict__ dupw,
                const float* __restrict__ bias,
                float* __restrict__ out, int OH, int OW)
{
    __shared__ float s_in[3][2][34][36];
    __shared__ __align__(16) float2 s_w[3][2 * ACC * 10];

    constexpr int GROUPS = COUT / ACC;
    constexpr int NS = CIN / 2;
    const int b   = blockIdx.z / GROUPS;
    const int grp = blockIdx.z % GROUPS;
    const int oc0 = grp * ACC;
    const int tid = threadIdx.x;
    const int tx = tid & 15, ty = tid >> 4;
    const int oy0 = blockIdx.y * 32, ox0 = blockIdx.x * 32;

    const int sr0 = tid >> 3;
    const int sc0 = tid & 7;

    u64 acc[ACC][2];
    #pragma unroll
    for (int i = 0; i < ACC; i++) {
        float bv = bias[oc0 + i];
        acc[i][0] = pk2(bv, bv);
        acc[i][1] = acc[i][0];
    }

    const unsigned inbase = sptr(&s_in[0][0][0][0]);
    const unsigned wbase  = sptr(&s_w[0][0]);
    const float2* wchunk = dupw + (size_t)grp * (CIN >> 1) * (2 * ACC * 10);
    const float* ipbase = in + (size_t)b * CIN * OH * OW;

    auto issue_stage = [&](int s) {
        const int buf = s % 3;
        const int c0 = 2 * s;
        #pragma unroll
        for (int cc = 0; cc < 2; cc++) {
            const float* ip = ipbase + (size_t)(c0 + cc) * OH * OW;
            unsigned sb = inbase + (unsigned)((buf * 2 + cc) * 34 * 36) * 4u;
            #pragma unroll
            for (int rp = 0; rp < 2; rp++) {
                int r = sr0 + rp * 32;
                if (rp == 0 || r < 34) {
                    int iy = oy0 - 1 + r;
                    bool rowok = (iy >= 0) && (iy < OH);
                    const float* iprow = ip + iy * OW;
                    unsigned srow = sb + (unsigned)(r * 36) * 4u;
                    #pragma unroll
                    for (int j = 0; j < 5; j++) {
                        int c = sc0 + 8 * j;
                        if (j < 4 || c < 34) {
                            int ix = ox0 - 1 + c;
                            bool ok = rowok && (ix >= 0) && (ix < OW);
                            const float* ga = ok ? (iprow + ix) : ip;
                            cp_async4(srow + (unsigned)c * 4u, ga, ok);
                        }
                    }
                }
            }
        }
        if (tid < ACC * 10) {
            const float2* wsrc = wchunk + (size_t)(c0 >> 1) * (2 * ACC * 10);
            cp_async16(wbase + (unsigned)(buf * 2 * ACC * 10 + tid * 2) * 8u,
                       wsrc + tid * 2);
        }
    };

    issue_stage(0); cp_commit();
    issue_stage(1); cp_commit();

    for (int s = 0; s < NS; s++) {
        const int buf = s % 3;
        cp_wait1();
        __syncthreads();

        #pragma unroll
        for (int cc = 0; cc < 2; cc++) {
            u64 pr[4][3];
            #pragma unroll
            for (int r = 0; r < 4; r++) {
                unsigned a = inbase + (unsigned)((buf * 2 + cc) * 34 * 36 + (2 * ty + r) * 36 + 2 * tx) * 4u;
                u64 A = lds_u64(a);
                u64 B = lds_u64(a + 8);
                float a0, a1, b0, b1;
                upk2(A, a0, a1); upk2(B, b0, b1);
                pr[r][0] = A; pr[r][1] = pk2(a1, b0); pr[r][2] = B;
            }
            #pragma unroll
            for (int i = 0; i < ACC; i++) {
                unsigned wa = wbase + (unsigned)(buf * 2 * ACC * 10) * 8u
                            + (unsigned)(cc * ACC + i) * 80u;
                u64 w[9];
                lds_v2u64(w[0], w[1], wa);
                lds_v2u64(w[2], w[3], wa + 16);
                lds_v2u64(w[4], w[5], wa + 32);
                lds_v2u64(w[6], w[7], wa + 48);
                w[8] = lds_u64(wa + 64);
                #pragma unroll
                for (int dy = 0; dy < 2; dy++)
                    #pragma unroll
                    for (int ky = 0; ky < 3; ky++)
                        #pragma unroll
                        for (int kx = 0; kx < 3; kx++)
                            fma2(acc[i][dy], pr[dy + ky][kx], w[ky * 3 + kx]);
            }
        }
        if (s + 2 < NS) issue_stage(s + 2);
        cp_commit();
    }

    const int oy = oy0 + 2 * ty, ox = ox0 + 2 * tx;
    #pragma unroll
    for (int i = 0; i < ACC; i++)
        #pragma unroll
        for (int dy = 0; dy < 2; dy++) {
            float v0, v1;
            upk2(acc[i][dy], v0, v1);
            if (ACT == 1) { v0 = fmaxf(v0, 0.f); v1 = fmaxf(v1, 0.f); }
            else if (ACT == 2) { v0 = 1.f / (1.f + expf(-v0)); v1 = 1.f / (1.f + expf(-v1)); }
            *reinterpret_cast<float2*>(out + (((size_t)b * COUT + oc0 + i) * OH + oy + dy) * OW + ox)
                = make_float2(v0, v1);
        }
}

// ============ dual-input stride-2 conv 3->64: single-shot cp.async staging ===
__global__ __launch_bounds__(256, 3)
void conv_s2_dual(const float* __restrict__ inA,
                  const float* __restrict__ inB,
                  const float* __restrict__ wt,
                  const float* __restrict__ bias,
                  float* __restrict__ out)
{
    constexpr int IT = 34;
    __shared__ float s_in[3][34][36];
    __shared__ float s_w[16 * 27];

    const int b   = blockIdx.z >> 2;
    const int oc0 = (blockIdx.z & 3) * 16;
    const float* in = (b < BATCH) ? inA + (size_t)b * 3 * 128 * 128
                                  : inB + (size_t)(b - BATCH) * 3 * 128 * 128;
    const int tid = threadIdx.x;
    const int tx = tid & 15, ty = tid >> 4;
    const int ox = blockIdx.x * 16 + tx;
    const int oy = blockIdx.y * 16 + ty;
    const int iy0 = blockIdx.y * 32;
    const int ix0 = blockIdx.x * 32;

    const unsigned inbase = sptr(&s_in[0][0][0]);
    const int sr0 = tid >> 3;
    const int sc0 = tid & 7;

    #pragma unroll
    for (int cc = 0; cc < 3; cc++) {
        const float* ip = in + (size_t)cc * 128 * 128;
        unsigned sb = inbase + (unsigned)(cc * 34 * 36) * 4u;
        #pragma unroll
        for (int rp = 0; rp < 2; rp++) {
            int r = sr0 + rp * 32;
            if (rp == 0 || r < IT) {
                int iy = iy0 + r;
                bool rowok = (iy < 128);
                const float* iprow = ip + iy * 128;
                unsigned srow = sb + (unsigned)(r * 36) * 4u;
                #pragma unroll
                for (int j = 0; j < 5; j++) {
                    int c = sc0 + 8 * j;
                    if (j < 4 || c < IT) {
                        int ix = ix0 + c;
                        bool ok = rowok && (ix < 128);
                        const float* ga = ok ? (iprow + ix) : ip;
                        cp_async4(srow + (unsigned)c * 4u, ga, ok);
                    }
                }
            }
        }
    }
    #pragma unroll
    for (int idx = tid; idx < 16 * 27; idx += 256) {
        int oc = idx / 27, k27 = idx % 27;
        int cin = k27 / 9, k = k27 % 9;
        cp_async4(sptr(&s_w[oc * 27 + k27]),
                  &wt[((size_t)(oc0 + oc) * 3 + cin) * 9 + k], true);
    }
    cp_commit();
    cp_wait0();
    __syncthreads();

    float acc[16];
    #pragma unroll
    for (int i = 0; i < 16; i++) acc[i] = bias[oc0 + i];

    #pragma unroll
    for (int cc = 0; cc < 3; cc++) {
        float p[3][3];
        #pragma unroll
        for (int ky = 0; ky < 3; ky++)
            #pragma unroll
            for (int kx = 0; kx < 3; kx++)
                p[ky][kx] = s_in[cc][ty * 2 + ky][tx * 2 + kx];
        #pragma unroll
        for (int ky = 0; ky < 3; ky++)
            #pragma unroll
            for (int kx = 0; kx < 3; kx++) {
                float v = p[ky][kx];
                #pragma unroll
                for (int i = 0; i < 16; i++)
                    acc[i] = fmaf(v, s_w[i * 27 + cc * 9 + ky * 3 + kx], acc[i]);
            }
    }

    #pragma unroll
    for (int i = 0; i < 16; i++)
        out[(((size_t)b * 64 + oc0 + i) * 64 + oy) * 64 + ox] = fmaxf(acc[i], 0.f);
}

// ============ parity-combined weights for upsample conv (d_w2) ============
__global__ void wc_precompute_kernel(const float* __restrict__ w2, float2* __restrict__ wc2)
{
    int t = blockIdx.x * 256 + threadIdx.x;
    if (t >= 32 * 64) return;
    int oc = t / 64, cin = t % 64;
    int grp = oc >> 4, i = oc & 15;
    float w[3][3];
    #pragma unroll
    for (int r = 0; r < 3; r++)
        #pragma unroll
        for (int c = 0; c < 3; c++)
            w[r][c] = w2[t * 9 + r * 3 + c];
    float ry[2][2][3];
    #pragma unroll
    for (int c = 0; c < 3; c++) {
        ry[0][0][c] = w[0][c];
        ry[0][1][c] = w[1][c] + w[2][c];
        ry[1][0][c] = w[0][c] + w[1][c];
        ry[1][1][c] = w[2][c];
    }
    float2* dst = wc2 + ((size_t)(grp * 64 + cin) * 16 + i) * 8;
    #pragma unroll
    for (int py = 0; py < 2; py++)
        #pragma unroll
        for (int dr = 0; dr < 2; dr++)
            #pragma unroll
            for (int dc = 0; dc < 2; dc++) {
                float v_px0 = (dc == 0) ? ry[py][dr][0] : (ry[py][dr][1] + ry[py][dr][2]);
                float v_px1 = (dc == 0) ? (ry[py][dr][0] + ry[py][dr][1]) : ry[py][dr][2];
                dst[py * 4 + dr * 2 + dc] = make_float2(v_px0, v_px1);
            }
}

// ============ pipelined parity conv: triple-buffered, one barrier/stage ======
__global__ __launch_bounds__(256, 2)
void parity_conv_kernel(const float* __restrict__ in,
                        const float2* __restrict__ wc2,
                        const float* __restrict__ bias,
                        float* __restrict__ out)
{
    __shared__ float s_in[3][18][20];
    __shared__ __align__(16) float2 s_w[3][128];

    const int b   = blockIdx.z >> 1;
    const int grp = blockIdx.z & 1;
    const int oc0 = grp * 16;
    const int tid = threadIdx.x;
    const int tx = tid & 15, ty = tid >> 4;
    const int i0 = blockIdx.y * 16, j0 = blockIdx.x * 16;

    const int sr0 = tid >> 4;
    const int scp = tid & 15;

    u64 acc[16][2];
    #pragma unroll
    for (int i = 0; i < 16; i++) {
        float bv = bias[oc0 + i];
        acc[i][0] = pk2(bv, bv);
        acc[i][1] = acc[i][0];
    }
    const unsigned inbase = sptr(&s_in[0][0][0]);
    const unsigned wbase = sptr(&s_w[0][0]);
    const float* ipbase = in + (size_t)b * 64 * 4096;
    const float2* wgrp = wc2 + (size_t)grp * 64 * 128;

    auto issue_stage = [&](int cin) {
        const int buf = cin % 3;
        const float* ip = ipbase + (size_t)cin * 4096;
        unsigned sb = inbase + (unsigned)(buf * 18 * 20) * 4u;
        #pragma unroll
        for (int rp = 0; rp < 2; rp++) {
            int r = sr0 + rp * 16;
            if (rp == 0 || r < 18) {
                int iy = i0 - 1 + r;
                bool rowok = (iy >= 0) && (iy < 64);
                const float* iprow = ip + iy * 64;
                unsigned srow = sb + (unsigned)(r * 20) * 4u;
                #pragma unroll
                for (int j = 0; j < 2; j++) {
                    int c = scp + 16 * j;
                    if (j == 0 || c < 18) {
                        int ix = j0 - 1 + c;
                        bool ok = rowok && (ix >= 0) && (ix < 64);
                        const float* ga = ok ? (iprow + ix) : ip;
                        cp_async4(srow + (unsigned)c * 4u, ga, ok);
                    }
                }
            }
        }
        if (tid < 64)
            cp_async16(wbase + (unsigned)(buf * 128 + tid * 2) * 8u,
                       wgrp + (size_t)cin * 128 + tid * 2);
    };

    issue_stage(0); cp_commit();
    issue_stage(1); cp_commit();

    for (int cin = 0; cin < 64; ++cin) {
        const int buf = cin % 3;
        cp_wait1();
        __syncthreads();

        float p[3][3];
        #pragma unroll
        for (int r = 0; r < 3; r++)
            #pragma unroll
            for (int c = 0; c < 3; c++)
                p[r][c] = s_in[buf][ty + r][tx + c];
        u64 q[3][2];
        #pragma unroll
        for (int r = 0; r < 3; r++) {
            q[r][0] = pk2(p[r][0], p[r][1]);
            q[r][1] = pk2(p[r][1], p[r][2]);
        }

        #pragma unroll
        for (int i = 0; i < 16; i++) {
            unsigned wa = wbase + (unsigned)(buf * 128) * 8u + i * 64u;
            u64 w[8];
            lds_v2u64(w[0], w[1], wa);
            lds_v2u64(w[2], w[3], wa + 16);
            lds_v2u64(w[4], w[5], wa + 32);
            lds_v2u64(w[6], w[7], wa + 48);
            #pragma unroll
            for (int py = 0; py < 2; py++)
                #pragma unroll
                for (int dr = 0; dr < 2; dr++)
                    #pragma unroll
                    for (int dc = 0; dc < 2; dc++)
                        fma2(acc[i][py], q[py + dr][dc], w[py * 4 + dr * 2 + dc]);
        }
        if (cin + 2 < 64) issue_stage(cin + 2);
        cp_commit();
    }

    const int oy2 = 2 * (i0 + ty), ox2 = 2 * (j0 + tx);
    #pragma unroll
    for (int i = 0; i < 16; i++)
        #pragma unroll
        for (int py = 0; py < 2; py++) {
            float v0, v1;
            upk2(acc[i][py], v0, v1);
            v0 = fmaxf(v0, 0.f); v1 = fmaxf(v1, 0.f);
            *reinterpret_cast<float2*>(out + (((size_t)b * 32 + oc0 + i) * 128 + oy2 + py) * 128 + ox2)
                = make_float2(v0, v1);
        }
}

// ------- fused spatial softmax + soft-argmax moments (both streams) -------
__global__ void softmax_mu_kernel(float* __restrict__ p,
                                  float* __restrict__ mu, float* __restrict__ Li,
                                  float* __restrict__ mua, float* __restrict__ Lia)
{
    float* base = p + (size_t)blockIdx.x * 4096;
    __shared__ float red[256];
    int tid = threadIdx.x;
    float m = -1e30f;
    float vals[16];
    #pragma unroll
    for (int j = 0; j < 16; j++) { vals[j] = base[tid + j * 256]; m = fmaxf(m, vals[j]); }
    red[tid] = m; __syncthreads();
    for (int s = 128; s > 0; s >>= 1) { if (tid < s) red[tid] = fmaxf(red[tid], red[tid + s]); __syncthreads(); }
    m = red[0]; __syncthreads();
    float sum = 0.f;
    #pragma unroll
    for (int j = 0; j < 16; j++) { vals[j] = expf(vals[j] - m); sum += vals[j]; }
    float tot = block_sum256(sum, red);
    float inv = 1.f / tot;
    float s0=0,s1=0,s2=0,s3=0,s4=0;
    #pragma unroll
    for (int j = 0; j < 16; j++) {
        int i = tid + j * 256;
        float pv = vals[j] * inv;
        base[i] = pv;
        int h = i >> 6, w = i & 63;
        float gy = -1.f + 2.f * h / 63.f;
        float gx = -1.f + 2.f * w / 63.f;
        s0 += pv * gy; s1 += pv * gx;
        s2 += pv * gy * gy; s3 += pv * gy * gx; s4 += pv * gx * gx;
    }
    s0 = block_sum256(s0, red);
    s1 = block_sum256(s1, red);
    s2 = block_sum256(s2, red);
    s3 = block_sum256(s3, red);
    s4 = block_sum256(s4, red);
    if (tid == 0) {
        float muy = s0, mux = s1;
        float c00 = s2 - muy * muy, c01 = s3 - muy * mux, c11 = s4 - mux * mux;
        float a  = sqrtf(c00 + EPSV);
        float bb = c01 / (a + EPSV);
        float c  = sqrtf(fmaxf(c11 - bb * bb, 0.f) + EPSV);
        float det = a * c;
        float sc = SCALV / (det + EPSV);
        int bk = blockIdx.x;
        float* pmu = (bk < 512) ? mu : mua;
        float* pLi = (bk < 512) ? Li : Lia;
        int o = bk & 511;
        pmu[o * 2 + 0] = muy; pmu[o * 2 + 1] = mux;
        pLi[o * 4 + 0] = sc * c;     pLi[o * 4 + 1] = 0.f;
        pLi[o * 4 + 2] = sc * (-bb); pLi[o * 4 + 3] = sc * a;
    }
}

// ---------------- alpha = einsum('bfhw,bkhw->bkf') ----------------
__global__ void alpha_kernel(const float* __restrict__ fxs,
                             const float* __restrict__ parts,
                             float* __restrict__ alpha)
{
    int bk = blockIdx.x;
    int b = bk >> 4;
    __shared__ float sp[4096];
    __shared__ float red[256];
    int tid = threadIdx.x;
    const float* pb = parts + (size_t)bk * 4096;
    for (int i = tid; i < 4096; i += 256) sp[i] = pb[i];
    __syncthreads();
    for (int f = 0; f < 32; f++) {
        const float* fb = fxs + ((size_t)b * 32 + f) * 4096;
        float s = 0.f;
        for (int i = tid; i < 4096; i += 256) s += fb[i] * sp[i];
        s = block_sum256(s, red);
        if (tid == 0) alpha[(size_t)bk * 32 + f] = s;
    }
}

// ---------------- Cauchy heat render + normalization ----------------
__global__ void heat_kernel(const float* __restrict__ mu, const float* __restrict__ Linv,
                            float* __restrict__ enc, float* __restrict__ norm)
{
    int bk = blockIdx.x;
    int b = bk >> 4, k = bk & 15;
    float muy = mu[bk*2], mux = mu[bk*2+1];
    float L00 = Linv[bk*4], L01 = Linv[bk*4+1], L10 = Linv[bk*4+2], L11 = Linv[bk*4+3];
    int tid = threadIdx.x;
    __shared__ float red[256];
    float hv[16]; float sum = 0.f;
    #pragma unroll
    for (int j = 0; j < 16; j++) {
        int i = tid + j * 256;
        int h = i >> 6, w = i & 63;
        float dy = (-1.f + 2.f * h / 63.f) - muy;
        float dx = (-1.f + 2.f * w / 63.f) - mux;
        float p0 = dy * L00 + dx * L10;
        float p1 = dy * L01 + dx * L11;
        float he = 1.f / (1.f + p0 * p0 + p1 * p1);
        hv[j] = he; sum += he;
    }
    float tot = block_sum256(sum, red);
    float inv = 1.f / (tot + EPSV);
    float* eb = enc + (((size_t)b * 48 + k) * 4096);
    float* nb = norm + (size_t)bk * 4096;
    #pragma unroll
    for (int j = 0; j < 16; j++) {
        int i = tid + j * 256;
        eb[i] = hv[j];
        nb[i] = hv[j] * inv;
    }
}

// ---------------- fmap = einsum('bkf,bkhw->bfhw') -> enc ch [16,48) ----------
__global__ void fmap_kernel(const float* __restrict__ alpha,
                            const float* __restrict__ norm,
                            float* __restrict__ enc)
{
    int b = blockIdx.y;
    int pix = blockIdx.x * 256 + threadIdx.x;
    __shared__ float sal[512];
    for (int i = threadIdx.x; i < 512; i += 256) sal[i] = alpha[(size_t)b * 512 + i];
    __syncthreads();
    float nv[16];
    #pragma unroll
    for (int k = 0; k < 16; k++) nv[k] = norm[((size_t)b * 16 + k) * 4096 + pix];
    #pragma unroll
    for (int f = 0; f < 32; f++) {
        float s = 0.f;
        #pragma unroll
        for (int k = 0; k < 16; k++) s = fmaf(sal[k * 32 + f], nv[k], s);
        enc[((size_t)b * 48 + 16 + f) * 4096 + pix] = s;
    }
}

// ---------------- losses ----------------
__global__ void rec_loss_partial_kernel(const float* __restrict__ x,
                                        const float* __restrict__ rec,
                                        float* __restrict__ partial)
{
    __shared__ float red[256];
    int i0 = blockIdx.x * 1024 + threadIdx.x;
    float s = 0.f;
    #pragma unroll
    for (int j = 0; j < 4; j++) {
        int i = i0 + j * 256;
        float d = x[i] - rec[i];
        s += d * d;
    }
    s = block_sum256(s, red);
    if (threadIdx.x == 0) partial[blockIdx.x] = s;
}

__global__ void final_loss_kernel(const float* __restrict__ partial,
                                  const float* __restrict__ mu, const float* __restrict__ Li,
                                  const float* __restrict__ mua, const float* __restrict__ Lia,
                                  const float* __restrict__ coord, const float* __restrict__ vec,
                                  float* __restrict__ out, int out_size)
{
    __shared__ float red[256];
    int tid = threadIdx.x;
    float s0=0,s1=0,s2=0,s3=0;
    for (int i = tid; i < 1536; i += 256) s0 += partial[i];
    for (int i = tid; i < 1024; i += 256) { float d = mu[i] - mua[i]; s1 += d * d; }
    for (int i = tid; i < 2048; i += 256) { float d = Li[i] - Lia[i]; s2 += d * d; }
    for (int i = tid; i < 1024; i += 256) { float d = mua[i] - (coord[i] + vec[i]); s3 += d * d; }
    s0 = block_sum256(s0, red);
    s1 = block_sum256(s1, red);
    s2 = block_sum256(s2, red);
    s3 = block_sum256(s3, red);
    if (tid == 0) {
        float loss = s0 / 1572864.f + s1 / 1024.f + 0.01f * (s2 / 2048.f) + s3 / 1024.f;
        if (out_size > 1572864) out[1572864] = loss;
    }
}

// ---------------- launch ----------------
extern "C" void kernel_launch(void* const* d_in, const int* in_sizes, int n_in,
                              void* d_out, int out_size)
{
    const float* x     = (const float*)d_in[0];
    const float* xsp   = (const float*)d_in[1];
    const float* xapp  = (const float*)d_in[2];
    const float* coord = (const float*)d_in[3];
    const float* vec   = (const float*)d_in[4];
    const float* es_w1 = (const float*)d_in[5];
    const float* es_b1 = (const float*)d_in[6];
    const float* es_w2 = (const float*)d_in[7];
    const float* es_b2 = (const float*)d_in[8];
    const float* es_wp = (const float*)d_in[9];
    const float* es_bp = (const float*)d_in[10];
    const float* ea_w1 = (const float*)d_in[11];
    const float* ea_b1 = (const float*)d_in[12];
    const float* ea_w2 = (const float*)d_in[13];
    const float* ea_b2 = (const float*)d_in[14];
    const float* d_w1  = (const float*)d_in[15];
    const float* d_b1  = (const float*)d_in[16];
    const float* d_w2  = (const float*)d_in[17];
    const float* d_b2  = (const float*)d_in[18];
    const float* d_w3  = (const float*)d_in[19];
    const float* d_b3  = (const float*)d_in[20];
    float* out = (float*)d_out;

    float *h1,*h2,*t1,*parts,*normb,*fxs,*enc,*h128,*mu,*Li,*mua,*Lia,*al,*part;
    float2 *wc2, *dupw;
    cudaGetSymbolAddress((void**)&h1, g_h1);
    cudaGetSymbolAddress((void**)&h2, g_h2);
    cudaGetSymbolAddress((void**)&t1, g_t1);
    cudaGetSymbolAddress((void**)&parts, g_parts);
    cudaGetSymbolAddress((void**)&normb, g_norm);
    cudaGetSymbolAddress((void**)&fxs, g_fxs);
    cudaGetSymbolAddress((void**)&enc, g_enc);
    cudaGetSymbolAddress((void**)&h128, g_h128);
    cudaGetSymbolAddress((void**)&mu, g_mu);
    cudaGetSymbolAddress((void**)&Li, g_Linv);
    cudaGetSymbolAddress((void**)&mua, g_mua);
    cudaGetSymbolAddress((void**)&Lia, g_Linva);
    cudaGetSymbolAddress((void**)&al, g_alpha);
    cudaGetSymbolAddress((void**)&part, g_partial);
    cudaGetSymbolAddress((void**)&wc2, g_wc2);
    cudaGetSymbolAddress((void**)&dupw, g_dupw);

    // opt-in dynamic smem for dy4 instantiations (idempotent host calls)
    cudaFuncSetAttribute(conv3x3_dy4<64,64,1>, cudaFuncAttributeMaxDynamicSharedMemorySize, DY4_SMEM);
    cudaFuncSetAttribute(conv3x3_dy4<64,16,0>, cudaFuncAttributeMaxDynamicSharedMemorySize, DY4_SMEM);
    cudaFuncSetAttribute(conv3x3_dy4<64,32,0>, cudaFuncAttributeMaxDynamicSharedMemorySize, DY4_SMEM);
    cudaFuncSetAttribute(conv3x3_dy4<48,64,1>, cudaFuncAttributeMaxDynamicSharedMemorySize, DY4_SMEM);

    const size_t IMG64 = (size_t)64 * 4096;
    const size_t PIMG  = (size_t)16 * 4096;

    dim3 blk(256);

    // Order: hot 64->64 conv is the 4th launch (ncu -s 5 -c 1 capture slot).
    dup_weights12_kernel<<<(64*64*12+255)/256, blk>>>(es_w2, dupw + OFF_ESW2, 64, 64);      // 1
    wc_precompute_kernel<<<8, blk>>>(d_w2, wc2);                                             // 2
    conv_s2_dual<<<dim3(4, 4, 256), blk>>>(xapp, xsp, es_w1, es_b1, h1);                     // 3
    conv3x3_dy4<64,64,1><<<dim3(2, 1, 512), blk, DY4_SMEM>>>(h1, dupw + OFF_ESW2, es_b2, h2, 64, 64); // 4
    dup_weights12_kernel<<<(16*64*12+255)/256, blk>>>(es_wp, dupw + OFF_ESWP, 16, 64);      // 5
    dup_weights12_kernel<<<(64*64*12+255)/256, blk>>>(ea_w1, dupw + OFF_EAW1, 64, 64);      // 6
    dup_weights12_kernel<<<(32*64*12+255)/256, blk>>>(ea_w2, dupw + OFF_EAW2, 32, 64);
    dup_weights12_kernel<<<(64*48*12+255)/256, blk>>>(d_w1,  dupw + OFF_DW1,  64, 48);
    dup_weights_kernel<<<(3*32*10+255)/256,  blk>>>(d_w3,  dupw + OFF_DW3,   3, 32, 3);

    conv3x3_dy4<64,16,0><<<dim3(2, 1, 128), blk, DY4_SMEM>>>(h2, dupw + OFF_ESWP, es_bp, parts, 64, 64);
    softmax_mu_kernel<<<1024, blk>>>(parts, mu, Li, mua, Lia);

    // ---- appearance-only tail ----
    conv3x3_dy4<64,64,1><<<dim3(2, 1, 256), blk, DY4_SMEM>>>(h2 + BATCH * IMG64, dupw + OFF_EAW1, ea_b1, t1, 64, 64);
    conv3x3_dy4<64,32,0><<<dim3(2, 1, 128), blk, DY4_SMEM>>>(t1, dupw + OFF_EAW2, ea_b2, fxs, 64, 64);
    alpha_kernel<<<512, blk>>>(fxs, parts + BATCH * PIMG, al);

    // ---- encoding ----
    heat_kernel<<<512, blk>>>(mu, Li, enc, normb);
    fmap_kernel<<<dim3(16, BATCH), blk>>>(al, normb, enc);

    // ---- decoder ----
    conv3x3_dy4<48,64,1><<<dim3(2, 1, 256), blk, DY4_SMEM>>>(enc, dupw + OFF_DW1, d_b1, t1, 64, 64);
    parity_conv_kernel<<<dim3(4, 4, 64), blk>>>(t1, wc2, d_b2, h128);
    conv3x3_f2<32,3,3,2><<<dim3(4, 4, 32), blk>>>(h128, dupw + OFF_DW3, d_b3, out, 128, 128);

    // ---- loss ----
    rec_loss_partial_kernel<<<1536, blk>>>(x, out, part);
    final_loss_kernel<<<1, blk>>>(part, mu, Li, mua, Lia, coord, vec, out, out_size);
}

// round 17
// speedup vs baseline: 1.0684x; 1.0684x over previous
#include <cuda_runtime.h>
#include <cuda_bf16.h>
#include <math.h>

#define BATCH 32
#define EPSV 1e-6f
#define SCALV 5.0f

typedef unsigned long long u64;

// ---------------- scratch (static device globals; alloc-free) ----------------
__device__ float g_h1[2*BATCH*64*64*64];
__device__ float g_h2[2*BATCH*64*64*64];
__device__ float g_t1[BATCH*64*64*64];
__device__ float g_parts[2*BATCH*16*64*64];
__device__ float g_norm[BATCH*16*64*64];
__device__ float g_fxs[BATCH*32*64*64];
__device__ float g_enc[BATCH*48*64*64];
__device__ float g_h128[BATCH*32*128*128];
__device__ float g_mu[BATCH*16*2];
__device__ float g_Linv[BATCH*16*4];
__device__ float g_mua[BATCH*16*2];
__device__ float g_Linva[BATCH*16*4];
__device__ float g_alpha[BATCH*16*32];
__device__ float g_partial[1536];
__device__ float2 g_wc2[2*64*16*8];          // parity weights [grp(2)][cin][i(16)][k(8)]

// dup-weight pool.
// 12-slot padded layout (dy4 kernels, ACC=8): [g][cin/2][(cc*8+i)*12 + ky*4 + kx]
// 10-slot layout (old kernel, final conv): unchanged
#define OFF_ESW2 0
#define OFF_ESWP (OFF_ESW2 + 64*64*12)
#define OFF_EAW1 (OFF_ESWP + 16*64*12)
#define OFF_EAW2 (OFF_EAW1 + 64*64*12)
#define OFF_DW1  (OFF_EAW2 + 32*64*12)
#define OFF_DW3  (OFF_DW1  + 64*48*12)
#define DUP_TOTAL (OFF_DW3 + 3*32*10)
__device__ float2 g_dupw[DUP_TOTAL];

// ---------------- f32x2 packed helpers ----------------
__device__ __forceinline__ u64 pk2(float lo, float hi) {
    u64 r; asm("mov.b64 %0, {%1, %2};" : "=l"(r) : "f"(lo), "f"(hi)); return r;
}
__device__ __forceinline__ void upk2(u64 v, float& lo, float& hi) {
    asm("mov.b64 {%0, %1}, %2;" : "=f"(lo), "=f"(hi) : "l"(v));
}
__device__ __forceinline__ void fma2(u64& d, u64 a, u64 b) {
    asm("fma.rn.f32x2 %0, %1, %2, %0;" : "+l"(d) : "l"(a), "l"(b));
}
__device__ __forceinline__ unsigned sptr(const void* p) {
    return (unsigned)__cvta_generic_to_shared(p);
}
__device__ __forceinline__ void lds_v2u64(u64& a, u64& b, unsigned addr) {
    asm volatile("ld.shared.v2.u64 {%0, %1}, [%2];" : "=l"(a), "=l"(b) : "r"(addr));
}
__device__ __forceinline__ u64 lds_u64(unsigned addr) {
    u64 r; asm volatile("ld.shared.b64 %0, [%1];" : "=l"(r) : "r"(addr)); return r;
}

// ---------------- cp.async helpers ----------------
__device__ __forceinline__ void cp_async4(unsigned saddr, const void* gaddr, bool ok) {
    asm volatile("cp.async.ca.shared.global [%0], [%1], 4, %2;"
                 :: "r"(saddr), "l"(gaddr), "r"(ok ? 4 : 0));
}
__device__ __forceinline__ void cp_async4s(unsigned saddr, const void* gaddr, int sz) {
    asm volatile("cp.async.ca.shared.global [%0], [%1], 4, %2;"
                 :: "r"(saddr), "l"(gaddr), "r"(sz));
}
__device__ __forceinline__ void cp_async8s(unsigned saddr, const void* gaddr, int sz) {
    asm volatile("cp.async.ca.shared.global [%0], [%1], 8, %2;"
                 :: "r"(saddr), "l"(gaddr), "r"(sz));
}
__device__ __forceinline__ void cp_async16(unsigned saddr, const void* gaddr) {
    asm volatile("cp.async.cg.shared.global [%0], [%1], 16;" :: "r"(saddr), "l"(gaddr));
}
__device__ __forceinline__ void cp_async16s(unsigned saddr, const void* gaddr, int sz) {
    asm volatile("cp.async.cg.shared.global [%0], [%1], 16, %2;"
                 :: "r"(saddr), "l"(gaddr), "r"(sz));
}
__device__ __forceinline__ void cp_commit() {
    asm volatile("cp.async.commit_group;");
}
__device__ __forceinline__ void cp_wait1() {
    asm volatile("cp.async.wait_group 1;");
}
__device__ __forceinline__ void cp_wait0() {
    asm volatile("cp.async.wait_group 0;");
}

// ---------------- reductions ----------------
__device__ __forceinline__ float warp_sum(float v) {
    #pragma unroll
    for (int o = 16; o; o >>= 1) v += __shfl_xor_sync(0xffffffffu, v, o);
    return v;
}
__device__ __forceinline__ float block_sum256(float v, float* red) {
    int tid = threadIdx.x;
    v = warp_sum(v);
    if ((tid & 31) == 0) red[tid >> 5] = v;
    __syncthreads();
    float r = 0.f;
    if (tid < 8) r = red[tid];
    if (tid < 32) r = warp_sum(r);
    if (tid == 0) red[0] = r;
    __syncthreads();
    float out = red[0];
    __syncthreads();
    return out;
}

// ============ weight duplication: 12-slot padded layout (dy4, ACC=8) ============
__global__ void dup_weights12_kernel(const float* __restrict__ src, float2* __restrict__ dst,
                                     int COUT, int CIN)
{
    int total = COUT * CIN * 12;
    int idx = blockIdx.x * 256 + threadIdx.x;
    if (idx >= total) return;
    int k12 = idx % 12;
    int t = idx / 12;
    int cin = t % CIN;
    int oc  = t / CIN;
    int g = oc >> 3, i = oc & 7;
    int c0h = cin >> 1, cc = cin & 1;
    int ky = k12 >> 2, kx = k12 & 3;
    float w = (kx < 3) ? src[((size_t)oc * CIN + cin) * 9 + ky * 3 + kx] : 0.f;
    dst[((size_t)(g * (CIN >> 1) + c0h) * (2 * 8 * 12)) + (cc * 8 + i) * 12 + k12] = make_float2(w, w);
}

// ============ weight duplication: 10-slot layout (old kernel) ============
__global__ void dup_weights_kernel(const float* __restrict__ src, float2* __restrict__ dst,
                                   int COUT, int CIN, int ACCv)
{
    int total = COUT * CIN * 10;
    int idx = blockIdx.x * 256 + threadIdx.x;
    if (idx >= total) return;
    int k = idx % 10;
    int t = idx / 10;
    int cin = t % CIN;
    int oc  = t / CIN;
    int g = oc / ACCv, i = oc % ACCv;
    int c0h = cin >> 1, cc = cin & 1;
    float w = (k < 9) ? src[((size_t)oc * CIN + cin) * 9 + k] : 0.f;
    dst[((size_t)(g * (CIN >> 1) + c0h) * 2 * ACCv + cc * ACCv + i) * 10 + k] = make_float2(w, w);
}

// ============ dy4 packed conv3x3 for 64x64 images, stride 1, SAME ============
// 64x32 tile (full height strip pair), 256 threads; each thread 4 rows x 1 pair
// x 8 channels. 16B-granule cp.async staging with hoisted offsets/predicates.
// Layout: img col c stored at word (c - ox0 + 4), row stride 40, rows r=img+1.
#define DY4_CH   (66 * 40)                       // floats per channel tile
#define DY4_SIN  (3 * 2 * DY4_CH)                // floats
#define DY4_SMEM (DY4_SIN * 4 + 3 * 192 * 8)     // bytes
template<int CIN, int COUT, int ACT>
__global__ __launch_bounds__(256, 2)
void conv3x3_dy4(const float* __restrict__ in,
                 const float2* __restrict__ dupw,
                 const float* __restrict__ bias,
                 float* __restrict__ out, int OH, int OW)
{
    extern __shared__ char dsm[];
    float* s_in = (float*)dsm;                       // [3][2][66][40]
    float2* s_w = (float2*)(dsm + DY4_SIN * 4);      // [3][192]

    constexpr int GROUPS = COUT / 8;
    constexpr int NS = CIN / 2;
    const int b   = blockIdx.z / GROUPS;
    const int grp = blockIdx.z % GROUPS;
    const int oc0 = grp * 8;
    const int tid = threadIdx.x;
    const int tx = tid & 15, ty = tid >> 4;
    const int ox0 = blockIdx.x * 32;

    // ---- stage-invariant per-thread staging precompute ----
    const int lane8 = tid & 7;
    const int r0 = tid >> 3;                 // rows r0, r0+32, r0+64 (last if r0<2)
    int goff[3], s16[3], smo[3], loff[3], lsz[3], roff[3], rsz[3];
    #pragma unroll
    for (int p = 0; p < 3; p++) {
        int r = r0 + 32 * p;
        int iy = r - 1;
        bool rowok = (iy >= 0) && (iy < 64);
        int iyc = min(max(iy, 0), 63);
        goff[p] = iyc * 64 + ox0 + 4 * lane8;
        s16[p]  = rowok ? 16 : 0;
        smo[p]  = r * 40 + 4 + 4 * lane8;
        loff[p] = iyc * 64 + max(ox0 - 1, 0);
        lsz[p]  = (rowok && ox0 > 0) ? 4 : 0;
        roff[p] = iyc * 64 + min(ox0 + 32, 63);
        rsz[p]  = (rowok && ox0 == 0) ? 8 : 0;
    }

    u64 acc[8][4];
    #pragma unroll
    for (int i = 0; i < 8; i++) {
        float bv = bias[oc0 + i];
        acc[i][0] = pk2(bv, bv);
        acc[i][1] = acc[i][0]; acc[i][2] = acc[i][0]; acc[i][3] = acc[i][0];
    }

    const unsigned inbase = sptr(s_in);
    const unsigned wbase  = sptr(s_w);
    const float2* wchunk = dupw + (size_t)grp * (CIN >> 1) * 192;
    const float* ipbase = in + (size_t)b * CIN * 4096;

    auto issue_stage = [&](int s) {
        const int buf = s % 3;
        const int c0 = 2 * s;
        #pragma unroll
        for (int cc = 0; cc < 2; cc++) {
            const float* ip = ipbase + (size_t)(c0 + cc) * 4096;
            unsigned sb = inbase + (unsigned)((buf * 2 + cc) * DY4_CH) * 4u;
            #pragma unroll
            for (int p = 0; p < 3; p++) {
                if (p < 2 || r0 < 2) {
                    cp_async16s(sb + (unsigned)smo[p] * 4u, ip + goff[p], s16[p]);
                    if (lane8 == 0)
                        cp_async4s(sb + (unsigned)(smo[p] - 1) * 4u, ip + loff[p], lsz[p]);
                    if (lane8 == 1)
                        cp_async8s(sb + (unsigned)(smo[p] + 28) * 4u, ip + roff[p], rsz[p]);
                }
            }
        }
        // weights: 192 float2 = 1536B = 96 x 16B
        if (tid < 96) {
            const float2* wsrc = wchunk + (size_t)(c0 >> 1) * 192;
            cp_async16(wbase + (unsigned)(buf * 192 + tid * 2) * 8u, wsrc + tid * 2);
        }
    };

    issue_stage(0); cp_commit();
    issue_stage(1); cp_commit();

    for (int s = 0; s < NS; s++) {
        const int buf = s % 3;
        cp_wait1();
        __syncthreads();

        #pragma unroll
        for (int cc = 0; cc < 2; cc++) {
            u64 pr[6][3];
            #pragma unroll
            for (int r = 0; r < 6; r++) {
                unsigned a = inbase + (unsigned)((buf * 2 + cc) * DY4_CH + (4 * ty + r) * 40 + 2 * tx + 2) * 4u;
                u64 A = lds_u64(a);
                u64 B = lds_u64(a + 8);
                u64 C = lds_u64(a + 16);
                float a0, a1, b0, b1, c0f, c1f;
                upk2(A, a0, a1); upk2(B, b0, b1); upk2(C, c0f, c1f);
                pr[r][0] = pk2(a1, b0);
                pr[r][1] = B;
                pr[r][2] = pk2(b1, c0f);
            }
            #pragma unroll
            for (int i = 0; i < 8; i++) {
                unsigned wa = wbase + (unsigned)(buf * 192 + (cc * 8 + i) * 12) * 8u;
                #pragma unroll
                for (int ky = 0; ky < 3; ky++) {
                    u64 w0, w1, w2;
                    lds_v2u64(w0, w1, wa + ky * 32);
                    w2 = lds_u64(wa + ky * 32 + 16);
                    #pragma unroll
                    for (int dy = 0; dy < 4; dy++) {
                        fma2(acc[i][dy], pr[dy + ky][0], w0);
                        fma2(acc[i][dy], pr[dy + ky][1], w1);
                        fma2(acc[i][dy], pr[dy + ky][2], w2);
                    }
                }
            }
        }
        if (s + 2 < NS) issue_stage(s + 2);
        cp_commit();
    }

    const int oy = 4 * ty, ox = ox0 + 2 * tx;
    #pragma unroll
    for (int i = 0; i < 8; i++)
        #pragma unroll
        for (int dy = 0; dy < 4; dy++) {
            float v0, v1;
            upk2(acc[i][dy], v0, v1);
            if (ACT == 1) { v0 = fmaxf(v0, 0.f); v1 = fmaxf(v1, 0.f); }
            else if (ACT == 2) { v0 = 1.f / (1.f + expf(-v0)); v1 = 1.f / (1.f + expf(-v1)); }
            *reinterpret_cast<float2*>(out + (((size_t)b * COUT + oc0 + i) * 64 + oy + dy) * 64 + ox)
                = make_float2(v0, v1);
        }
}

// ============ old packed conv3x3 (kept for the 32->3 final conv) ============
template<int CIN, int COUT, int ACC, int ACT>
__global__ __launch_bounds__(256, 2)
void conv3x3_f2(const float* __restrict__ in,
                const float2* __restrict__ dupw,
                const float* __restrict__ bias,
                float* __restrict__ out, int OH, int OW)
{
    __shared__ float s_in[3][2][34][36];
    __shared__ __align__(16) float2 s_w[3][2 * ACC * 10];

    constexpr int GROUPS = COUT / ACC;
    constexpr int NS = CIN / 2;
    const int b   = blockIdx.z / GROUPS;
    const int grp = blockIdx.z % GROUPS;
    const int oc0 = grp * ACC;
    const int tid = threadIdx.x;
    const int tx = tid & 15, ty = tid >> 4;
    const int oy0 = blockIdx.y * 32, ox0 = blockIdx.x * 32;

    const int sr0 = tid >> 3;
    const int sc0 = tid & 7;

    u64 acc[ACC][2];
    #pragma unroll
    for (int i = 0; i < ACC; i++) {
        float bv = bias[oc0 + i];
        acc[i][0] = pk2(bv, bv);
        acc[i][1] = acc[i][0];
    }

    const unsigned inbase = sptr(&s_in[0][0][0][0]);
    const unsigned wbase  = sptr(&s_w[0][0]);
    const float2* wchunk = dupw + (size_t)grp * (CIN >> 1) * (2 * ACC * 10);
    const float* ipbase = in + (size_t)b * CIN * OH * OW;

    auto issue_stage = [&](int s) {
        const int buf = s % 3;
        const int c0 = 2 * s;
        #pragma unroll
        for (int cc = 0; cc < 2; cc++) {
            const float* ip = ipbase + (size_t)(c0 + cc) * OH * OW;
            unsigned sb = inbase + (unsigned)((buf * 2 + cc) * 34 * 36) * 4u;
            #pragma unroll
            for (int rp = 0; rp < 2; rp++) {
                int r = sr0 + rp * 32;
                if (rp == 0 || r < 34) {
                    int iy = oy0 - 1 + r;
                    bool rowok = (iy >= 0) && (iy < OH);
                    const float* iprow = ip + iy * OW;
                    unsigned srow = sb + (unsigned)(r * 36) * 4u;
                    #pragma unroll
                    for (int j = 0; j < 5; j++) {
                        int c = sc0 + 8 * j;
                        if (j < 4 || c < 34) {
                            int ix = ox0 - 1 + c;
                            bool ok = rowok && (ix >= 0) && (ix < OW);
                            const float* ga = ok ? (iprow + ix) : ip;
                            cp_async4(srow + (unsigned)c * 4u, ga, ok);
                        }
                    }
                }
            }
        }
        if (tid < ACC * 10) {
            const float2* wsrc = wchunk + (size_t)(c0 >> 1) * (2 * ACC * 10);
            cp_async16(wbase + (unsigned)(buf * 2 * ACC * 10 + tid * 2) * 8u,
                       wsrc + tid * 2);
        }
    };

    issue_stage(0); cp_commit();
    issue_stage(1); cp_commit();

    for (int s = 0; s < NS; s++) {
        const int buf = s % 3;
        cp_wait1();
        __syncthreads();

        #pragma unroll
        for (int cc = 0; cc < 2; cc++) {
            u64 pr[4][3];
            #pragma unroll
            for (int r = 0; r < 4; r++) {
                unsigned a = inbase + (unsigned)((buf * 2 + cc) * 34 * 36 + (2 * ty + r) * 36 + 2 * tx) * 4u;
                u64 A = lds_u64(a);
                u64 B = lds_u64(a + 8);
                float a0, a1, b0, b1;
                upk2(A, a0, a1); upk2(B, b0, b1);
                pr[r][0] = A; pr[r][1] = pk2(a1, b0); pr[r][2] = B;
            }
            #pragma unroll
            for (int i = 0; i < ACC; i++) {
                unsigned wa = wbase + (unsigned)(buf * 2 * ACC * 10) * 8u
                            + (unsigned)(cc * ACC + i) * 80u;
                u64 w[9];
                lds_v2u64(w[0], w[1], wa);
                lds_v2u64(w[2], w[3], wa + 16);
                lds_v2u64(w[4], w[5], wa + 32);
                lds_v2u64(w[6], w[7], wa + 48);
                w[8] = lds_u64(wa + 64);
                #pragma unroll
                for (int dy = 0; dy < 2; dy++)
                    #pragma unroll
                    for (int ky = 0; ky < 3; ky++)
                        #pragma unroll
                        for (int kx = 0; kx < 3; kx++)
                            fma2(acc[i][dy], pr[dy + ky][kx], w[ky * 3 + kx]);
            }
        }
        if (s + 2 < NS) issue_stage(s + 2);
        cp_commit();
    }

    const int oy = oy0 + 2 * ty, ox = ox0 + 2 * tx;
    #pragma unroll
    for (int i = 0; i < ACC; i++)
        #pragma unroll
        for (int dy = 0; dy < 2; dy++) {
            float v0, v1;
            upk2(acc[i][dy], v0, v1);
            if (ACT == 1) { v0 = fmaxf(v0, 0.f); v1 = fmaxf(v1, 0.f); }
            else if (ACT == 2) { v0 = 1.f / (1.f + expf(-v0)); v1 = 1.f / (1.f + expf(-v1)); }
            *reinterpret_cast<float2*>(out + (((size_t)b * COUT + oc0 + i) * OH + oy + dy) * OW + ox)
                = make_float2(v0, v1);
        }
}

// ============ dual-input stride-2 conv 3->64: single-shot cp.async staging ===
__global__ __launch_bounds__(256, 3)
void conv_s2_dual(const float* __restrict__ inA,
                  const float* __restrict__ inB,
                  const float* __restrict__ wt,
                  const float* __restrict__ bias,
                  float* __restrict__ out)
{
    constexpr int IT = 34;
    __shared__ float s_in[3][34][36];
    __shared__ float s_w[16 * 27];

    const int b   = blockIdx.z >> 2;
    const int oc0 = (blockIdx.z & 3) * 16;
    const float* in = (b < BATCH) ? inA + (size_t)b * 3 * 128 * 128
                                  : inB + (size_t)(b - BATCH) * 3 * 128 * 128;
    const int tid = threadIdx.x;
    const int tx = tid & 15, ty = tid >> 4;
    const int ox = blockIdx.x * 16 + tx;
    const int oy = blockIdx.y * 16 + ty;
    const int iy0 = blockIdx.y * 32;
    const int ix0 = blockIdx.x * 32;

    const unsigned inbase = sptr(&s_in[0][0][0]);
    const int sr0 = tid >> 3;
    const int sc0 = tid & 7;

    #pragma unroll
    for (int cc = 0; cc < 3; cc++) {
        const float* ip = in + (size_t)cc * 128 * 128;
        unsigned sb = inbase + (unsigned)(cc * 34 * 36) * 4u;
        #pragma unroll
        for (int rp = 0; rp < 2; rp++) {
            int r = sr0 + rp * 32;
            if (rp == 0 || r < IT) {
                int iy = iy0 + r;
                bool rowok = (iy < 128);
                const float* iprow = ip + iy * 128;
                unsigned srow = sb + (unsigned)(r * 36) * 4u;
                #pragma unroll
                for (int j = 0; j < 5; j++) {
                    int c = sc0 + 8 * j;
                    if (j < 4 || c < IT) {
                        int ix = ix0 + c;
                        bool ok = rowok && (ix < 128);
                        const float* ga = ok ? (iprow + ix) : ip;
                        cp_async4(srow + (unsigned)c * 4u, ga, ok);
                    }
                }
            }
        }
    }
    #pragma unroll
    for (int idx = tid; idx < 16 * 27; idx += 256) {
        int oc = idx / 27, k27 = idx % 27;
        int cin = k27 / 9, k = k27 % 9;
        cp_async4(sptr(&s_w[oc * 27 + k27]),
                  &wt[((size_t)(oc0 + oc) * 3 + cin) * 9 + k], true);
    }
    cp_commit();
    cp_wait0();
    __syncthreads();

    float acc[16];
    #pragma unroll
    for (int i = 0; i < 16; i++) acc[i] = bias[oc0 + i];

    #pragma unroll
    for (int cc = 0; cc < 3; cc++) {
        float p[3][3];
        #pragma unroll
        for (int ky = 0; ky < 3; ky++)
            #pragma unroll
            for (int kx = 0; kx < 3; kx++)
                p[ky][kx] = s_in[cc][ty * 2 + ky][tx * 2 + kx];
        #pragma unroll
        for (int ky = 0; ky < 3; ky++)
            #pragma unroll
            for (int kx = 0; kx < 3; kx++) {
                float v = p[ky][kx];
                #pragma unroll
                for (int i = 0; i < 16; i++)
                    acc[i] = fmaf(v, s_w[i * 27 + cc * 9 + ky * 3 + kx], acc[i]);
            }
    }

    #pragma unroll
    for (int i = 0; i < 16; i++)
        out[(((size_t)b * 64 + oc0 + i) * 64 + oy) * 64 + ox] = fmaxf(acc[i], 0.f);
}

// ============ parity-combined weights for upsample conv (d_w2) ============
__global__ void wc_precompute_kernel(const float* __restrict__ w2, float2* __restrict__ wc2)
{
    int t = blockIdx.x * 256 + threadIdx.x;
    if (t >= 32 * 64) return;
    int oc = t / 64, cin = t % 64;
    int grp = oc >> 4, i = oc & 15;
    float w[3][3];
    #pragma unroll
    for (int r = 0; r < 3; r++)
        #pragma unroll
        for (int c = 0; c < 3; c++)
            w[r][c] = w2[t * 9 + r * 3 + c];
    float ry[2][2][3];
    #pragma unroll
    for (int c = 0; c < 3; c++) {
        ry[0][0][c] = w[0][c];
        ry[0][1][c] = w[1][c] + w[2][c];
        ry[1][0][c] = w[0][c] + w[1][c];
        ry[1][1][c] = w[2][c];
    }
    float2* dst = wc2 + ((size_t)(grp * 64 + cin) * 16 + i) * 8;
    #pragma unroll
    for (int py = 0; py < 2; py++)
        #pragma unroll
        for (int dr = 0; dr < 2; dr++)
            #pragma unroll
            for (int dc = 0; dc < 2; dc++) {
                float v_px0 = (dc == 0) ? ry[py][dr][0] : (ry[py][dr][1] + ry[py][dr][2]);
                float v_px1 = (dc == 0) ? (ry[py][dr][0] + ry[py][dr][1]) : ry[py][dr][2];
                dst[py * 4 + dr * 2 + dc] = make_float2(v_px0, v_px1);
            }
}

// ============ pipelined parity conv: triple-buffered, one barrier/stage ======
__global__ __launch_bounds__(256, 2)
void parity_conv_kernel(const float* __restrict__ in,
                        const float2* __restrict__ wc2,
                        const float* __restrict__ bias,
                        float* __restrict__ out)
{
    __shared__ float s_in[3][18][20];
    __shared__ __align__(16) float2 s_w[3][128];

    const int b   = blockIdx.z >> 1;
    const int grp = blockIdx.z & 1;
    const int oc0 = grp * 16;
    const int tid = threadIdx.x;
    const int tx = tid & 15, ty = tid >> 4;
    const int i0 = blockIdx.y * 16, j0 = blockIdx.x * 16;

    const int sr0 = tid >> 4;
    const int scp = tid & 15;

    u64 acc[16][2];
    #pragma unroll
    for (int i = 0; i < 16; i++) {
        float bv = bias[oc0 + i];
        acc[i][0] = pk2(bv, bv);
        acc[i][1] = acc[i][0];
    }
    const unsigned inbase = sptr(&s_in[0][0][0]);
    const unsigned wbase = sptr(&s_w[0][0]);
    const float* ipbase = in + (size_t)b * 64 * 4096;
    const float2* wgrp = wc2 + (size_t)grp * 64 * 128;

    auto issue_stage = [&](int cin) {
        const int buf = cin % 3;
        const float* ip = ipbase + (size_t)cin * 4096;
        unsigned sb = inbase + (unsigned)(buf * 18 * 20) * 4u;
        #pragma unroll
        for (int rp = 0; rp < 2; rp++) {
            int r = sr0 + rp * 16;
            if (rp == 0 || r < 18) {
                int iy = i0 - 1 + r;
                bool rowok = (iy >= 0) && (iy < 64);
                const float* iprow = ip + iy * 64;
                unsigned srow = sb + (unsigned)(r * 20) * 4u;
                #pragma unroll
                for (int j = 0; j < 2; j++) {
                    int c = scp + 16 * j;
                    if (j == 0 || c < 18) {
                        int ix = j0 - 1 + c;
                        bool ok = rowok && (ix >= 0) && (ix < 64);
                        const float* ga = ok ? (iprow + ix) : ip;
                        cp_async4(srow + (unsigned)c * 4u, ga, ok);
                    }
                }
            }
        }
        if (tid < 64)
            cp_async16(wbase + (unsigned)(buf * 128 + tid * 2) * 8u,
                       wgrp + (size_t)cin * 128 + tid * 2);
    };

    issue_stage(0); cp_commit();
    issue_stage(1); cp_commit();

    for (int cin = 0; cin < 64; ++cin) {
        const int buf = cin % 3;
        cp_wait1();
        __syncthreads();

        float p[3][3];
        #pragma unroll
        for (int r = 0; r < 3; r++)
            #pragma unroll
            for (int c = 0; c < 3; c++)
                p[r][c] = s_in[buf][ty + r][tx + c];
        u64 q[3][2];
        #pragma unroll
        for (int r = 0; r < 3; r++) {
            q[r][0] = pk2(p[r][0], p[r][1]);
            q[r][1] = pk2(p[r][1], p[r][2]);
        }

        #pragma unroll
        for (int i = 0; i < 16; i++) {
            unsigned wa = wbase + (unsigned)(buf * 128) * 8u + i * 64u;
            u64 w[8];
            lds_v2u64(w[0], w[1], wa);
            lds_v2u64(w[2], w[3], wa + 16);
            lds_v2u64(w[4], w[5], wa + 32);
            lds_v2u64(w[6], w[7], wa + 48);
            #pragma unroll
            for (int py = 0; py < 2; py++)
                #pragma unroll
                for (int dr = 0; dr < 2; dr++)
                    #pragma unroll
                    for (int dc = 0; dc < 2; dc++)
                        fma2(acc[i][py], q[py + dr][dc], w[py * 4 + dr * 2 + dc]);
        }
        if (cin + 2 < 64) issue_stage(cin + 2);
        cp_commit();
    }

    const int oy2 = 2 * (i0 + ty), ox2 = 2 * (j0 + tx);
    #pragma unroll
    for (int i = 0; i < 16; i++)
        #pragma unroll
        for (int py = 0; py < 2; py++) {
            float v0, v1;
            upk2(acc[i][py], v0, v1);
            v0 = fmaxf(v0, 0.f); v1 = fmaxf(v1, 0.f);
            *reinterpret_cast<float2*>(out + (((size_t)b * 32 + oc0 + i) * 128 + oy2 + py) * 128 + ox2)
                = make_float2(v0, v1);
        }
}

// ------- fused spatial softmax + soft-argmax moments (both streams) -------
__global__ void softmax_mu_kernel(float* __restrict__ p,
                                  float* __restrict__ mu, float* __restrict__ Li,
                                  float* __restrict__ mua, float* __restrict__ Lia)
{
    float* base = p + (size_t)blockIdx.x * 4096;
    __shared__ float red[256];
    int tid = threadIdx.x;
    float m = -1e30f;
    float vals[16];
    #pragma unroll
    for (int j = 0; j < 16; j++) { vals[j] = base[tid + j * 256]; m = fmaxf(m, vals[j]); }
    red[tid] = m; __syncthreads();
    for (int s = 128; s > 0; s >>= 1) { if (tid < s) red[tid] = fmaxf(red[tid], red[tid + s]); __syncthreads(); }
    m = red[0]; __syncthreads();
    float sum = 0.f;
    #pragma unroll
    for (int j = 0; j < 16; j++) { vals[j] = expf(vals[j] - m); sum += vals[j]; }
    float tot = block_sum256(sum, red);
    float inv = 1.f / tot;
    float s0=0,s1=0,s2=0,s3=0,s4=0;
    #pragma unroll
    for (int j = 0; j < 16; j++) {
        int i = tid + j * 256;
        float pv = vals[j] * inv;
        base[i] = pv;
        int h = i >> 6, w = i & 63;
        float gy = -1.f + 2.f * h / 63.f;
        float gx = -1.f + 2.f * w / 63.f;
        s0 += pv * gy; s1 += pv * gx;
        s2 += pv * gy * gy; s3 += pv * gy * gx; s4 += pv * gx * gx;
    }
    s0 = block_sum256(s0, red);
    s1 = block_sum256(s1, red);
    s2 = block_sum256(s2, red);
    s3 = block_sum256(s3, red);
    s4 = block_sum256(s4, red);
    if (tid == 0) {
        float muy = s0, mux = s1;
        float c00 = s2 - muy * muy, c01 = s3 - muy * mux, c11 = s4 - mux * mux;
        float a  = sqrtf(c00 + EPSV);
        float bb = c01 / (a + EPSV);
        float c  = sqrtf(fmaxf(c11 - bb * bb, 0.f) + EPSV);
        float det = a * c;
        float sc = SCALV / (det + EPSV);
        int bk = blockIdx.x;
        float* pmu = (bk < 512) ? mu : mua;
        float* pLi = (bk < 512) ? Li : Lia;
        int o = bk & 511;
        pmu[o * 2 + 0] = muy; pmu[o * 2 + 1] = mux;
        pLi[o * 4 + 0] = sc * c;     pLi[o * 4 + 1] = 0.f;
        pLi[o * 4 + 2] = sc * (-bb); pLi[o * 4 + 3] = sc * a;
    }
}

// ---------------- alpha = einsum('bfhw,bkhw->bkf') ----------------
__global__ void alpha_kernel(const float* __restrict__ fxs,
                             const float* __restrict__ parts,
                             float* __restrict__ alpha)
{
    int bk = blockIdx.x;
    int b = bk >> 4;
    __shared__ float sp[4096];
    __shared__ float red[256];
    int tid = threadIdx.x;
    const float* pb = parts + (size_t)bk * 4096;
    for (int i = tid; i < 4096; i += 256) sp[i] = pb[i];
    __syncthreads();
    for (int f = 0; f < 32; f++) {
        const float* fb = fxs + ((size_t)b * 32 + f) * 4096;
        float s = 0.f;
        for (int i = tid; i < 4096; i += 256) s += fb[i] * sp[i];
        s = block_sum256(s, red);
        if (tid == 0) alpha[(size_t)bk * 32 + f] = s;
    }
}

// ---------------- Cauchy heat render + normalization ----------------
__global__ void heat_kernel(const float* __restrict__ mu, const float* __restrict__ Linv,
                            float* __restrict__ enc, float* __restrict__ norm)
{
    int bk = blockIdx.x;
    int b = bk >> 4, k = bk & 15;
    float muy = mu[bk*2], mux = mu[bk*2+1];
    float L00 = Linv[bk*4], L01 = Linv[bk*4+1], L10 = Linv[bk*4+2], L11 = Linv[bk*4+3];
    int tid = threadIdx.x;
    __shared__ float red[256];
    float hv[16]; float sum = 0.f;
    #pragma unroll
    for (int j = 0; j < 16; j++) {
        int i = tid + j * 256;
        int h = i >> 6, w = i & 63;
        float dy = (-1.f + 2.f * h / 63.f) - muy;
        float dx = (-1.f + 2.f * w / 63.f) - mux;
        float p0 = dy * L00 + dx * L10;
        float p1 = dy * L01 + dx * L11;
        float he = 1.f / (1.f + p0 * p0 + p1 * p1);
        hv[j] = he; sum += he;
    }
    float tot = block_sum256(sum, red);
    float inv = 1.f / (tot + EPSV);
    float* eb = enc + (((size_t)b * 48 + k) * 4096);
    float* nb = norm + (size_t)bk * 4096;
    #pragma unroll
    for (int j = 0; j < 16; j++) {
        int i = tid + j * 256;
        eb[i] = hv[j];
        nb[i] = hv[j] * inv;
    }
}

// ---------------- fmap = einsum('bkf,bkhw->bfhw') -> enc ch [16,48) ----------
__global__ void fmap_kernel(const float* __restrict__ alpha,
                            const float* __restrict__ norm,
                            float* __restrict__ enc)
{
    int b = blockIdx.y;
    int pix = blockIdx.x * 256 + threadIdx.x;
    __shared__ float sal[512];
    for (int i = threadIdx.x; i < 512; i += 256) sal[i] = alpha[(size_t)b * 512 + i];
    __syncthreads();
    float nv[16];
    #pragma unroll
    for (int k = 0; k < 16; k++) nv[k] = norm[((size_t)b * 16 + k) * 4096 + pix];
    #pragma unroll
    for (int f = 0; f < 32; f++) {
        float s = 0.f;
        #pragma unroll
        for (int k = 0; k < 16; k++) s = fmaf(sal[k * 32 + f], nv[k], s);
        enc[((size_t)b * 48 + 16 + f) * 4096 + pix] = s;
    }
}

// ---------------- losses ----------------
__global__ void rec_loss_partial_kernel(const float* __restrict__ x,
                                        const float* __restrict__ rec,
                                        float* __restrict__ partial)
{
    __shared__ float red[256];
    int i0 = blockIdx.x * 1024 + threadIdx.x;
    float s = 0.f;
    #pragma unroll
    for (int j = 0; j < 4; j++) {
        int i = i0 + j * 256;
        float d = x[i] - rec[i];
        s += d * d;
    }
    s = block_sum256(s, red);
    if (threadIdx.x == 0) partial[blockIdx.x] = s;
}

__global__ void final_loss_kernel(const float* __restrict__ partial,
                                  const float* __restrict__ mu, const float* __restrict__ Li,
                                  const float* __restrict__ mua, const float* __restrict__ Lia,
                                  const float* __restrict__ coord, const float* __restrict__ vec,
                                  float* __restrict__ out, int out_size)
{
    __shared__ float red[256];
    int tid = threadIdx.x;
    float s0=0,s1=0,s2=0,s3=0;
    for (int i = tid; i < 1536; i += 256) s0 += partial[i];
    for (int i = tid; i < 1024; i += 256) { float d = mu[i] - mua[i]; s1 += d * d; }
    for (int i = tid; i < 2048; i += 256) { float d = Li[i] - Lia[i]; s2 += d * d; }
    for (int i = tid; i < 1024; i += 256) { float d = mua[i] - (coord[i] + vec[i]); s3 += d * d; }
    s0 = block_sum256(s0, red);
    s1 = block_sum256(s1, red);
    s2 = block_sum256(s2, red);
    s3 = block_sum256(s3, red);
    if (tid == 0) {
        float loss = s0 / 1572864.f + s1 / 1024.f + 0.01f * (s2 / 2048.f) + s3 / 1024.f;
        if (out_size > 1572864) out[1572864] = loss;
    }
}

// ---------------- launch ----------------
extern "C" void kernel_launch(void* const* d_in, const int* in_sizes, int n_in,
                              void* d_out, int out_size)
{
    const float* x     = (const float*)d_in[0];
    const float* xsp   = (const float*)d_in[1];
    const float* xapp  = (const float*)d_in[2];
    const float* coord = (const float*)d_in[3];
    const float* vec   = (const float*)d_in[4];
    const float* es_w1 = (const float*)d_in[5];
    const float* es_b1 = (const float*)d_in[6];
    const float* es_w2 = (const float*)d_in[7];
    const float* es_b2 = (const float*)d_in[8];
    const float* es_wp = (const float*)d_in[9];
    const float* es_bp = (const float*)d_in[10];
    const float* ea_w1 = (const float*)d_in[11];
    const float* ea_b1 = (const float*)d_in[12];
    const float* ea_w2 = (const float*)d_in[13];
    const float* ea_b2 = (const float*)d_in[14];
    const float* d_w1  = (const float*)d_in[15];
    const float* d_b1  = (const float*)d_in[16];
    const float* d_w2  = (const float*)d_in[17];
    const float* d_b2  = (const float*)d_in[18];
    const float* d_w3  = (const float*)d_in[19];
    const float* d_b3  = (const float*)d_in[20];
    float* out = (float*)d_out;

    float *h1,*h2,*t1,*parts,*normb,*fxs,*enc,*h128,*mu,*Li,*mua,*Lia,*al,*part;
    float2 *wc2, *dupw;
    cudaGetSymbolAddress((void**)&h1, g_h1);
    cudaGetSymbolAddress((void**)&h2, g_h2);
    cudaGetSymbolAddress((void**)&t1, g_t1);
    cudaGetSymbolAddress((void**)&parts, g_parts);
    cudaGetSymbolAddress((void**)&normb, g_norm);
    cudaGetSymbolAddress((void**)&fxs, g_fxs);
    cudaGetSymbolAddress((void**)&enc, g_enc);
    cudaGetSymbolAddress((void**)&h128, g_h128);
    cudaGetSymbolAddress((void**)&mu, g_mu);
    cudaGetSymbolAddress((void**)&Li, g_Linv);
    cudaGetSymbolAddress((void**)&mua, g_mua);
    cudaGetSymbolAddress((void**)&Lia, g_Linva);
    cudaGetSymbolAddress((void**)&al, g_alpha);
    cudaGetSymbolAddress((void**)&part, g_partial);
    cudaGetSymbolAddress((void**)&wc2, g_wc2);
    cudaGetSymbolAddress((void**)&dupw, g_dupw);

    // opt-in dynamic smem for dy4 instantiations (idempotent host calls)
    cudaFuncSetAttribute(conv3x3_dy4<64,64,1>, cudaFuncAttributeMaxDynamicSharedMemorySize, DY4_SMEM);
    cudaFuncSetAttribute(conv3x3_dy4<64,16,0>, cudaFuncAttributeMaxDynamicSharedMemorySize, DY4_SMEM);
    cudaFuncSetAttribute(conv3x3_dy4<64,32,0>, cudaFuncAttributeMaxDynamicSharedMemorySize, DY4_SMEM);
    cudaFuncSetAttribute(conv3x3_dy4<48,64,1>, cudaFuncAttributeMaxDynamicSharedMemorySize, DY4_SMEM);

    const size_t IMG64 = (size_t)64 * 4096;
    const size_t PIMG  = (size_t)16 * 4096;

    dim3 blk(256);

    // Order: hot 64->64 conv is the 4th launch (ncu -s 5 -c 1 capture slot).
    dup_weights12_kernel<<<(64*64*12+255)/256, blk>>>(es_w2, dupw + OFF_ESW2, 64, 64);      // 1
    wc_precompute_kernel<<<8, blk>>>(d_w2, wc2);                                             // 2
    conv_s2_dual<<<dim3(4, 4, 256), blk>>>(xapp, xsp, es_w1, es_b1, h1);                     // 3
    conv3x3_dy4<64,64,1><<<dim3(2, 1, 512), blk, DY4_SMEM>>>(h1, dupw + OFF_ESW2, es_b2, h2, 64, 64); // 4
    dup_weights12_kernel<<<(16*64*12+255)/256, blk>>>(es_wp, dupw + OFF_ESWP, 16, 64);      // 5
    dup_weights12_kernel<<<(64*64*12+255)/256, blk>>>(ea_w1, dupw + OFF_EAW1, 64, 64);      // 6
    dup_weights12_kernel<<<(32*64*12+255)/256, blk>>>(ea_w2, dupw + OFF_EAW2, 32, 64);
    dup_weights12_kernel<<<(64*48*12+255)/256, blk>>>(d_w1,  dupw + OFF_DW1,  64, 48);
    dup_weights_kernel<<<(3*32*10+255)/256,  blk>>>(d_w3,  dupw + OFF_DW3,   3, 32, 3);

    conv3x3_dy4<64,16,0><<<dim3(2, 1, 128), blk, DY4_SMEM>>>(h2, dupw + OFF_ESWP, es_bp, parts, 64, 64);
    softmax_mu_kernel<<<1024, blk>>>(parts, mu, Li, mua, Lia);

    // ---- appearance-only tail ----
    conv3x3_dy4<64,64,1><<<dim3(2, 1, 256), blk, DY4_SMEM>>>(h2 + BATCH * IMG64, dupw + OFF_EAW1, ea_b1, t1, 64, 64);
    conv3x3_dy4<64,32,0><<<dim3(2, 1, 128), blk, DY4_SMEM>>>(t1, dupw + OFF_EAW2, ea_b2, fxs, 64, 64);
    alpha_kernel<<<512, blk>>>(fxs, parts + BATCH * PIMG, al);

    // ---- encoding ----
    heat_kernel<<<512, blk>>>(mu, Li, enc, normb);
    fmap_kernel<<<dim3(16, BATCH), blk>>>(al, normb, enc);

    // ---- decoder ----
    conv3x3_dy4<48,64,1><<<dim3(2, 1, 256), blk, DY4_SMEM>>>(enc, dupw + OFF_DW1, d_b1, t1, 64, 64);
    parity_conv_kernel<<<dim3(4, 4, 64), blk>>>(t1, wc2, d_b2, h128);
    conv3x3_f2<32,3,3,2><<<dim3(4, 4, 32), blk>>>(h128, dupw + OFF_DW3, d_b3, out, 128, 128);

    // ---- loss ----
    rec_loss_partial_kernel<<<1536, blk>>>(x, out, part);
    final_loss_kernel<<<1, blk>>>(part, mu, Li, mua, Lia, coord, vec, out, out_size);
}